// round 1
// baseline (speedup 1.0000x reference)
#include <cuda_runtime.h>
#include <math.h>

// Problem constants
#define BB 4
#define RR 16384
#define SS 96
#define NRAY (BB*RR)       // 65536 rays
#define SMID (SS-1)        // 95 mid samples

// Output packing offsets (floats), tuple order:
// composite_rgb (B,R,3), composite_depth (B,R,1), weights (B,R,95,1),
// composite_point (B,R,3), tau (B,R,1)
#define RGB_OFF   0
#define DEPTH_OFF (NRAY*3)                 // 196608
#define W_OFF     (DEPTH_OFF + NRAY)       // 262144
#define PT_OFF    (W_OFF + NRAY*SMID)      // 6488064
#define TAU_OFF   (PT_OFF + NRAY*3)        // 6684672

// Global min/max of depths (bit-encoded non-negative floats: monotone as uint)
__device__ unsigned int g_min_bits;
__device__ unsigned int g_max_bits;

__global__ void init_minmax_kernel() {
    g_min_bits = 0x7f800000u;  // +inf
    g_max_bits = 0x00000000u;  // 0.0f (depths are uniform [0,1), non-negative)
}

// Depths are sorted along S: per-ray min = depths[ray*S], max = depths[ray*S + S-1].
__global__ void minmax_kernel(const float* __restrict__ depths) {
    int t = blockIdx.x * blockDim.x + threadIdx.x;
    float lo = INFINITY, hi = 0.0f;
    if (t < NRAY) {
        lo = depths[(size_t)t * SS];
        hi = depths[(size_t)t * SS + (SS - 1)];
    }
    #pragma unroll
    for (int o = 16; o > 0; o >>= 1) {
        lo = fminf(lo, __shfl_down_sync(0xffffffffu, lo, o));
        hi = fmaxf(hi, __shfl_down_sync(0xffffffffu, hi, o));
    }
    __shared__ float slo[8], shi[8];
    int w = threadIdx.x >> 5, l = threadIdx.x & 31;
    if (l == 0) { slo[w] = lo; shi[w] = hi; }
    __syncthreads();
    if (threadIdx.x == 0) {
        int nw = blockDim.x >> 5;
        for (int i = 1; i < nw; i++) { lo = fminf(lo, slo[i]); hi = fmaxf(hi, shi[i]); }
        atomicMin(&g_min_bits, __float_as_uint(lo));
        atomicMax(&g_max_bits, __float_as_uint(hi));
    }
}

// One warp per ray. 95 mid samples processed in 3 chunks of 32 lanes with a
// warp-shuffle prefix-product for the transmittance cumprod.
__global__ void __launch_bounds__(256) march_kernel(
    const float* __restrict__ colors,
    const float* __restrict__ dens,
    const float* __restrict__ depths,
    const float* __restrict__ coords,
    const int*   __restrict__ wb,
    float* __restrict__ out)
{
    const unsigned FULL = 0xffffffffu;
    int gwarp = (blockIdx.x * blockDim.x + threadIdx.x) >> 5;
    int lane  = threadIdx.x & 31;
    if (gwarp >= NRAY) return;

    const size_t r1 = (size_t)gwarp * SS;
    const size_t r3 = r1 * 3;

    float T = 1.0f;                 // transmittance carry across chunks
    float srgb0 = 0.f, srgb1 = 0.f, srgb2 = 0.f;
    float spt0 = 0.f, spt1 = 0.f, spt2 = 0.f;
    float sd = 0.f, sw = 0.f;
    float tau = 0.f;                // recorded at i == SMID-1 (trans before last factor)

    float* __restrict__ wout = out + W_OFF + (size_t)gwarp * SMID;

    #pragma unroll
    for (int c = 0; c < 3; c++) {
        int i = c * 32 + lane;
        bool valid = (i < SMID);

        float alpha = 0.f, f = 1.f;
        float dmid = 0.f, cm0 = 0.f, cm1 = 0.f, cm2 = 0.f;
        float pm0 = 0.f, pm1 = 0.f, pm2 = 0.f;

        if (valid) {
            float d0 = depths[r1 + i];
            float d1 = depths[r1 + i + 1];
            float delta = d1 - d0;
            dmid = 0.5f * (d0 + d1);

            float e0 = dens[r1 + i];
            float e1 = dens[r1 + i + 1];
            float dm = 0.5f * (e0 + e1);
            // softplus(x) = max(x,0) + log1p(exp(-|x|))  (== jnp.logaddexp(x,0))
            float sp = fmaxf(dm, 0.f) + log1pf(expf(-fabsf(dm)));
            alpha = 1.0f - expf(-sp * delta);
            f = 1.0f - alpha + 1e-10f;

            size_t b0 = r3 + (size_t)3 * i;
            size_t b1 = b0 + 3;
            cm0 = 0.5f * (colors[b0 + 0] + colors[b1 + 0]);
            cm1 = 0.5f * (colors[b0 + 1] + colors[b1 + 1]);
            cm2 = 0.5f * (colors[b0 + 2] + colors[b1 + 2]);
            pm0 = 0.5f * (coords[b0 + 0] + coords[b1 + 0]);
            pm1 = 0.5f * (coords[b0 + 1] + coords[b1 + 1]);
            pm2 = 0.5f * (coords[b0 + 2] + coords[b1 + 2]);
        }

        // Inclusive prefix product of f across the warp
        float incl = f;
        #pragma unroll
        for (int o = 1; o < 32; o <<= 1) {
            float v = __shfl_up_sync(FULL, incl, o);
            if (lane >= o) incl *= v;
        }
        // Exclusive prefix
        float excl = __shfl_up_sync(FULL, incl, 1);
        if (lane == 0) excl = 1.0f;

        float Ti = T * excl;          // trans_i
        float w  = alpha * Ti;        // weight_i

        if (valid) {
            wout[i] = w;
            srgb0 += w * cm0; srgb1 += w * cm1; srgb2 += w * cm2;
            spt0  += w * pm0; spt1  += w * pm1; spt2  += w * pm2;
            sd += w * dmid;
            sw += w;
            if (i == SMID - 1) tau = Ti;
        }

        T *= __shfl_sync(FULL, incl, 31);  // carry full-chunk product
    }

    // Warp reductions (tau is nonzero on exactly one lane, so sum works)
    #pragma unroll
    for (int o = 16; o > 0; o >>= 1) {
        srgb0 += __shfl_down_sync(FULL, srgb0, o);
        srgb1 += __shfl_down_sync(FULL, srgb1, o);
        srgb2 += __shfl_down_sync(FULL, srgb2, o);
        spt0  += __shfl_down_sync(FULL, spt0,  o);
        spt1  += __shfl_down_sync(FULL, spt1,  o);
        spt2  += __shfl_down_sync(FULL, spt2,  o);
        sd    += __shfl_down_sync(FULL, sd,    o);
        sw    += __shfl_down_sync(FULL, sw,    o);
        tau   += __shfl_down_sync(FULL, tau,   o);
    }

    if (lane == 0) {
        float d = sd;
        if (isnan(d)) d = INFINITY;   // nan_to_num(nan=inf)
        float lo = __uint_as_float(g_min_bits);
        float hi = __uint_as_float(g_max_bits);
        d = fminf(fmaxf(d, lo), hi);  // clip; +inf -> hi

        float add = (wb[0] != 0) ? (1.0f - sw) : 0.0f;

        int w3 = gwarp * 3;
        out[RGB_OFF + w3 + 0] = srgb0 + add;
        out[RGB_OFF + w3 + 1] = srgb1 + add;
        out[RGB_OFF + w3 + 2] = srgb2 + add;
        out[DEPTH_OFF + gwarp] = d;
        out[PT_OFF + w3 + 0] = spt0;
        out[PT_OFF + w3 + 1] = spt1;
        out[PT_OFF + w3 + 2] = spt2;
        out[TAU_OFF + gwarp] = tau;
    }
}

extern "C" void kernel_launch(void* const* d_in, const int* in_sizes, int n_in,
                              void* d_out, int out_size) {
    const float* colors = (const float*)d_in[0];
    const float* dens   = (const float*)d_in[1];
    const float* depths = (const float*)d_in[2];
    const float* coords = (const float*)d_in[3];
    const int*   wb     = (const int*)d_in[4];
    float* out = (float*)d_out;

    init_minmax_kernel<<<1, 1>>>();
    minmax_kernel<<<(NRAY + 255) / 256, 256>>>(depths);
    // 8 warps (rays) per 256-thread block
    march_kernel<<<NRAY / 8, 256>>>(colors, dens, depths, coords, wb, out);
}